// round 10
// baseline (speedup 1.0000x reference)
#include <cuda_runtime.h>
#include <cuda_bf16.h>
#include <cstdint>

// y = x @ w + b  (exact collapse of the memristor model; G_off / K_V / k_g all
// cancel).  3-term bf16-split GEMM on legacy mma.sync tensor cores:
//   y ~= xh@wh + xl@wh + xh@wl   (fp32 accum, rel err ~2^-16)
// 128 CTAs x 512 thr = 8 col-groups x 16 k-chunk producers.
// NO grid barrier: per-group acq_rel ticket; the last-arriving producer of a
// column group reduces that group's 16 partials + bias (L2-hot) itself.
// Others exit. No spinning -> no co-residency requirement.

#define NIN 1024
#define NOUT 512
#define BATCH 128
#define KCHUNKS 16
#define KCHUNK 64
#define CTILE 64
#define NTHR 512
#define BN (BATCH * NOUT)

#define ASTRIDE 72            // bf16 row stride (144 B) -> conflict-free frags
#define A_ROWS 128
#define B_ROWS 64

#define OFF_AHI 0
#define OFF_ALO (OFF_AHI + A_ROWS * ASTRIDE)
#define OFF_BHI (OFF_ALO + A_ROWS * ASTRIDE)
#define OFF_BLO (OFF_BHI + B_ROWS * ASTRIDE)
#define SMEM_ELEMS (OFF_BLO + B_ROWS * ASTRIDE)
#define SMEM_BYTES (SMEM_ELEMS * 2)          // 55296 B

__device__ float g_partial[KCHUNKS * BN];    // 4 MB scratch
__device__ unsigned g_tick[8];               // per-group monotonic tickets

__device__ __forceinline__ uint32_t packbf(float a, float b) {
    __nv_bfloat162 h = __floats2bfloat162_rn(a, b);   // a -> low 16 bits
    return *reinterpret_cast<uint32_t*>(&h);
}
__device__ __forceinline__ uint64_t pack64(uint32_t lo, uint32_t hi) {
    uint64_t r; asm("mov.b64 %0, {%1, %2};" : "=l"(r) : "r"(lo), "r"(hi)); return r;
}
__device__ __forceinline__ void mma_bf16(float* c, const uint32_t* a, const uint32_t* b) {
    asm volatile(
        "mma.sync.aligned.m16n8k16.row.col.f32.bf16.bf16.f32 "
        "{%0,%1,%2,%3}, {%4,%5,%6,%7}, {%8,%9}, {%0,%1,%2,%3};"
        : "+f"(c[0]), "+f"(c[1]), "+f"(c[2]), "+f"(c[3])
        : "r"(a[0]), "r"(a[1]), "r"(a[2]), "r"(a[3]), "r"(b[0]), "r"(b[1]));
}

__global__ __launch_bounds__(NTHR) void fused_kernel(
    const float* __restrict__ X, const float* __restrict__ W,
    const float* __restrict__ B, float* __restrict__ out)
{
    extern __shared__ __nv_bfloat16 sm[];
    __nv_bfloat16* Ahi = sm + OFF_AHI;
    __nv_bfloat16* Alo = sm + OFF_ALO;
    __nv_bfloat16* Bhi = sm + OFF_BHI;
    __nv_bfloat16* Blo = sm + OFF_BLO;

    const int t = threadIdx.x, bid = blockIdx.x;
    const int warp = t >> 5, lane = t & 31;
    const int g  = lane >> 2;          // group row 0..7
    const int tq = lane & 3;           // thread-in-group 0..3
    const int grp = bid & 7;           // column group 0..7
    const int c0  = grp * CTILE;
    const int kc0 = (bid >> 3) * KCHUNK;      // k-chunk 0..15

    // ---- fill A: X[128 rows x 64 k] -> hi/lo bf16.  128*16 float4 = 2048. ----
    #pragma unroll
    for (int i = 0; i < 4; ++i) {
        int idx = t + i * NTHR;                // 0..2047
        int kq = idx & 15, row = idx >> 4;     // row 0..127
        float4 xv = *reinterpret_cast<const float4*>(&X[row * NIN + kc0 + 4 * kq]);
        float h0 = __bfloat162float(__float2bfloat16(xv.x));
        float h1 = __bfloat162float(__float2bfloat16(xv.y));
        float h2 = __bfloat162float(__float2bfloat16(xv.z));
        float h3 = __bfloat162float(__float2bfloat16(xv.w));
        int e = row * ASTRIDE + 4 * kq;        // 144*row + 8*kq bytes: 8B-aligned
        *reinterpret_cast<uint64_t*>(&Ahi[e]) = pack64(packbf(h0, h1), packbf(h2, h3));
        *reinterpret_cast<uint64_t*>(&Alo[e]) =
            pack64(packbf(xv.x - h0, xv.y - h1), packbf(xv.z - h2, xv.w - h3));
    }
    // ---- fill B: W[64k x 64n] -> [n][k] hi/lo bf16 pairs. 64n*32kp = 2048. ----
    #pragma unroll
    for (int i = 0; i < 4; ++i) {
        int idx = t + i * NTHR;                // 0..2047
        int n = idx & 63, kp = idx >> 6;       // lanes: consecutive n -> coalesced
        float w0 = W[(kc0 + 2 * kp) * NOUT + c0 + n];
        float w1 = W[(kc0 + 2 * kp + 1) * NOUT + c0 + n];
        float h0 = __bfloat162float(__float2bfloat16(w0));
        float h1 = __bfloat162float(__float2bfloat16(w1));
        *reinterpret_cast<uint32_t*>(&Bhi[n * ASTRIDE + 2 * kp]) = packbf(h0, h1);
        *reinterpret_cast<uint32_t*>(&Blo[n * ASTRIDE + 2 * kp]) = packbf(w0 - h0, w1 - h1);
    }
    __syncthreads();

    // ---- phase 1 compute: warp = rows 16*(w>>1).., cols 32*(w&1).. ----
    float acc[4][4];
    #pragma unroll
    for (int j = 0; j < 4; ++j)
        #pragma unroll
        for (int q = 0; q < 4; ++q) acc[j][q] = 0.f;

    const int wr  = warp >> 1;
    const int cn0 = (warp & 1) * 32;
    const int arow0 = (wr * 16 + g) * ASTRIDE;
    const int arow1 = arow0 + 8 * ASTRIDE;

    #pragma unroll
    for (int kk = 0; kk < 4; ++kk) {
        const int kb = kk * 16 + 2 * tq;
        uint32_t ah[4], al[4];
        ah[0] = *reinterpret_cast<const uint32_t*>(&Ahi[arow0 + kb]);
        ah[1] = *reinterpret_cast<const uint32_t*>(&Ahi[arow1 + kb]);
        ah[2] = *reinterpret_cast<const uint32_t*>(&Ahi[arow0 + kb + 8]);
        ah[3] = *reinterpret_cast<const uint32_t*>(&Ahi[arow1 + kb + 8]);
        al[0] = *reinterpret_cast<const uint32_t*>(&Alo[arow0 + kb]);
        al[1] = *reinterpret_cast<const uint32_t*>(&Alo[arow1 + kb]);
        al[2] = *reinterpret_cast<const uint32_t*>(&Alo[arow0 + kb + 8]);
        al[3] = *reinterpret_cast<const uint32_t*>(&Alo[arow1 + kb + 8]);

        uint32_t bh[4][2], bl[4][2];
        #pragma unroll
        for (int j = 0; j < 4; ++j) {
            const int brow = (cn0 + 8 * j + g) * ASTRIDE;
            bh[j][0] = *reinterpret_cast<const uint32_t*>(&Bhi[brow + kb]);
            bh[j][1] = *reinterpret_cast<const uint32_t*>(&Bhi[brow + kb + 8]);
            bl[j][0] = *reinterpret_cast<const uint32_t*>(&Blo[brow + kb]);
            bl[j][1] = *reinterpret_cast<const uint32_t*>(&Blo[brow + kb + 8]);
        }
        #pragma unroll
        for (int j = 0; j < 4; ++j) mma_bf16(acc[j], ah, bh[j]);
        #pragma unroll
        for (int j = 0; j < 4; ++j) mma_bf16(acc[j], al, bh[j]);
        #pragma unroll
        for (int j = 0; j < 4; ++j) mma_bf16(acc[j], ah, bl[j]);
    }

    // ---- store partials ----
    {
        float* part = g_partial + (bid >> 3) * BN;
        const int r0 = wr * 16 + g;
        #pragma unroll
        for (int j = 0; j < 4; ++j) {
            const int col = c0 + cn0 + 8 * j + 2 * tq;
            *reinterpret_cast<float2*>(&part[r0 * NOUT + col])       = make_float2(acc[j][0], acc[j][1]);
            *reinterpret_cast<float2*>(&part[(r0 + 8) * NOUT + col]) = make_float2(acc[j][2], acc[j][3]);
        }
    }

    // ---- arrival: last producer of this column group becomes the reducer ----
    __shared__ int s_last;
    __syncthreads();                 // all partial STGs issued by this CTA
    if (t == 0) {
        unsigned my;
        asm volatile("atom.add.acq_rel.gpu.global.u32 %0, [%1], 1;"
                     : "=r"(my) : "l"(&g_tick[grp]) : "memory");
        s_last = ((my & 15u) == 15u);   // monotonic ticket: wrap-safe over replays
    }
    __syncthreads();
    if (!s_last) return;             // 15 of 16 CTAs exit immediately

    // ---- reduce this group's 16 partials + bias (L2-hot, fixed order) ----
    // Group outputs: 128 rows x 64 cols = 2048 float4; 4 per thread.
    #pragma unroll
    for (int i = 0; i < 4; ++i) {
        int f4 = t + i * NTHR;                 // 0..2047
        int row = f4 >> 4, cc4 = f4 & 15;
        int o = row * NOUT + c0 + cc4 * 4;
        float4 s0 = make_float4(0.f, 0.f, 0.f, 0.f);
        float4 s1 = make_float4(0.f, 0.f, 0.f, 0.f);
        #pragma unroll
        for (int p = 0; p < 8; ++p) {          // two 8-partial passes: fixed order,
            float4 a = *reinterpret_cast<const float4*>(&g_partial[p * BN + o]);
            float4 b = *reinterpret_cast<const float4*>(&g_partial[(p + 8) * BN + o]);
            s0.x += a.x; s0.y += a.y; s0.z += a.z; s0.w += a.w;
            s1.x += b.x; s1.y += b.y; s1.z += b.z; s1.w += b.w;
        }
        float4 bv = *reinterpret_cast<const float4*>(&B[c0 + cc4 * 4]);
        *reinterpret_cast<float4*>(&out[o]) = make_float4(
            s0.x + s1.x + bv.x, s0.y + s1.y + bv.y,
            s0.z + s1.z + bv.z, s0.w + s1.w + bv.w);
    }
}

extern "C" void kernel_launch(void* const* d_in, const int* in_sizes, int n_in,
                              void* d_out, int out_size)
{
    const float* X = (const float*)d_in[0];  // (128, 1024)
    const float* W = (const float*)d_in[1];  // (1024, 512)
    const float* B = (const float*)d_in[2];  // (512,)
    float* out = (float*)d_out;              // (128, 512)

    cudaFuncSetAttribute(fused_kernel, cudaFuncAttributeMaxDynamicSharedMemorySize, SMEM_BYTES);
    fused_kernel<<<128, NTHR, SMEM_BYTES>>>(X, W, B, out);
}

// round 12
// speedup vs baseline: 1.4019x; 1.4019x over previous
#include <cuda_runtime.h>
#include <cuda_bf16.h>
#include <cstdint>

// y = x @ w + b  (exact collapse of the memristor model; G_off / K_V / k_g all
// cancel).  3-term bf16-split GEMM on legacy mma.sync tensor cores:
//   y ~= xh@wh + xl@wh + xh@wl   (fp32 accum, rel err ~2^-16)
// 128 CTAs x 512 thr = 8 col-groups x 16 k-chunk producers.
// Coordination: PER-GROUP release/acquire spin barrier (16 CTAs each, all 128
// co-resident in one wave), then all 16 group CTAs reduce 1/16 of the group's
// outputs each (spread, L2-hot).  Phase 1 identical to the round-8 best.

#define NIN 1024
#define NOUT 512
#define BATCH 128
#define KCHUNKS 16
#define KCHUNK 64
#define CTILE 64
#define NTHR 512
#define BN (BATCH * NOUT)

#define ASTRIDE 72            // bf16 row stride (144 B) -> conflict-free frags
#define A_ROWS 128
#define B_ROWS 64

#define OFF_AHI 0
#define OFF_ALO (OFF_AHI + A_ROWS * ASTRIDE)
#define OFF_BHI (OFF_ALO + A_ROWS * ASTRIDE)
#define OFF_BLO (OFF_BHI + B_ROWS * ASTRIDE)
#define SMEM_ELEMS (OFF_BLO + B_ROWS * ASTRIDE)
#define SMEM_BYTES (SMEM_ELEMS * 2)          // 55296 B

__device__ float g_partial[KCHUNKS * BN];    // 4 MB scratch
__device__ unsigned g_tick[8];               // per-group monotonic tickets

__device__ __forceinline__ uint32_t packbf(float a, float b) {
    __nv_bfloat162 h = __floats2bfloat162_rn(a, b);   // a -> low 16 bits
    return *reinterpret_cast<uint32_t*>(&h);
}
__device__ __forceinline__ uint64_t pack64(uint32_t lo, uint32_t hi) {
    uint64_t r; asm("mov.b64 %0, {%1, %2};" : "=l"(r) : "r"(lo), "r"(hi)); return r;
}
__device__ __forceinline__ void mma_bf16(float* c, const uint32_t* a, const uint32_t* b) {
    asm volatile(
        "mma.sync.aligned.m16n8k16.row.col.f32.bf16.bf16.f32 "
        "{%0,%1,%2,%3}, {%4,%5,%6,%7}, {%8,%9}, {%0,%1,%2,%3};"
        : "+f"(c[0]), "+f"(c[1]), "+f"(c[2]), "+f"(c[3])
        : "r"(a[0]), "r"(a[1]), "r"(a[2]), "r"(a[3]), "r"(b[0]), "r"(b[1]));
}

__global__ __launch_bounds__(NTHR) void fused_kernel(
    const float* __restrict__ X, const float* __restrict__ W,
    const float* __restrict__ B, float* __restrict__ out)
{
    extern __shared__ __nv_bfloat16 sm[];
    __nv_bfloat16* Ahi = sm + OFF_AHI;
    __nv_bfloat16* Alo = sm + OFF_ALO;
    __nv_bfloat16* Bhi = sm + OFF_BHI;
    __nv_bfloat16* Blo = sm + OFF_BLO;

    const int t = threadIdx.x, bid = blockIdx.x;
    const int warp = t >> 5, lane = t & 31;
    const int g  = lane >> 2;          // group row 0..7
    const int tq = lane & 3;           // thread-in-group 0..3
    const int grp = bid & 7;           // column group 0..7
    const int c0  = grp * CTILE;
    const int kc0 = (bid >> 3) * KCHUNK;      // k-chunk 0..15

    // ---- fill A: X[128 rows x 64 k] -> hi/lo bf16.  128*16 float4 = 2048. ----
    #pragma unroll
    for (int i = 0; i < 4; ++i) {
        int idx = t + i * NTHR;                // 0..2047
        int kq = idx & 15, row = idx >> 4;     // row 0..127
        float4 xv = *reinterpret_cast<const float4*>(&X[row * NIN + kc0 + 4 * kq]);
        float h0 = __bfloat162float(__float2bfloat16(xv.x));
        float h1 = __bfloat162float(__float2bfloat16(xv.y));
        float h2 = __bfloat162float(__float2bfloat16(xv.z));
        float h3 = __bfloat162float(__float2bfloat16(xv.w));
        int e = row * ASTRIDE + 4 * kq;        // 144*row + 8*kq bytes: 8B-aligned
        *reinterpret_cast<uint64_t*>(&Ahi[e]) = pack64(packbf(h0, h1), packbf(h2, h3));
        *reinterpret_cast<uint64_t*>(&Alo[e]) =
            pack64(packbf(xv.x - h0, xv.y - h1), packbf(xv.z - h2, xv.w - h3));
    }
    // ---- fill B: W[64k x 64n] -> [n][k] hi/lo bf16 pairs. 64n*32kp = 2048. ----
    #pragma unroll
    for (int i = 0; i < 4; ++i) {
        int idx = t + i * NTHR;                // 0..2047
        int n = idx & 63, kp = idx >> 6;       // lanes: consecutive n -> coalesced
        float w0 = W[(kc0 + 2 * kp) * NOUT + c0 + n];
        float w1 = W[(kc0 + 2 * kp + 1) * NOUT + c0 + n];
        float h0 = __bfloat162float(__float2bfloat16(w0));
        float h1 = __bfloat162float(__float2bfloat16(w1));
        *reinterpret_cast<uint32_t*>(&Bhi[n * ASTRIDE + 2 * kp]) = packbf(h0, h1);
        *reinterpret_cast<uint32_t*>(&Blo[n * ASTRIDE + 2 * kp]) = packbf(w0 - h0, w1 - h1);
    }
    __syncthreads();

    // ---- phase 1 compute: warp = rows 16*(w>>1).., cols 32*(w&1).. ----
    float acc[4][4];
    #pragma unroll
    for (int j = 0; j < 4; ++j)
        #pragma unroll
        for (int q = 0; q < 4; ++q) acc[j][q] = 0.f;

    const int wr  = warp >> 1;
    const int cn0 = (warp & 1) * 32;
    const int arow0 = (wr * 16 + g) * ASTRIDE;
    const int arow1 = arow0 + 8 * ASTRIDE;

    #pragma unroll
    for (int kk = 0; kk < 4; ++kk) {
        const int kb = kk * 16 + 2 * tq;
        uint32_t ah[4], al[4];
        ah[0] = *reinterpret_cast<const uint32_t*>(&Ahi[arow0 + kb]);
        ah[1] = *reinterpret_cast<const uint32_t*>(&Ahi[arow1 + kb]);
        ah[2] = *reinterpret_cast<const uint32_t*>(&Ahi[arow0 + kb + 8]);
        ah[3] = *reinterpret_cast<const uint32_t*>(&Ahi[arow1 + kb + 8]);
        al[0] = *reinterpret_cast<const uint32_t*>(&Alo[arow0 + kb]);
        al[1] = *reinterpret_cast<const uint32_t*>(&Alo[arow1 + kb]);
        al[2] = *reinterpret_cast<const uint32_t*>(&Alo[arow0 + kb + 8]);
        al[3] = *reinterpret_cast<const uint32_t*>(&Alo[arow1 + kb + 8]);

        uint32_t bh[4][2], bl[4][2];
        #pragma unroll
        for (int j = 0; j < 4; ++j) {
            const int brow = (cn0 + 8 * j + g) * ASTRIDE;
            bh[j][0] = *reinterpret_cast<const uint32_t*>(&Bhi[brow + kb]);
            bh[j][1] = *reinterpret_cast<const uint32_t*>(&Bhi[brow + kb + 8]);
            bl[j][0] = *reinterpret_cast<const uint32_t*>(&Blo[brow + kb]);
            bl[j][1] = *reinterpret_cast<const uint32_t*>(&Blo[brow + kb + 8]);
        }
        #pragma unroll
        for (int j = 0; j < 4; ++j) mma_bf16(acc[j], ah, bh[j]);
        #pragma unroll
        for (int j = 0; j < 4; ++j) mma_bf16(acc[j], al, bh[j]);
        #pragma unroll
        for (int j = 0; j < 4; ++j) mma_bf16(acc[j], ah, bl[j]);
    }

    // ---- store partials ----
    {
        float* part = g_partial + (bid >> 3) * BN;
        const int r0 = wr * 16 + g;
        #pragma unroll
        for (int j = 0; j < 4; ++j) {
            const int col = c0 + cn0 + 8 * j + 2 * tq;
            *reinterpret_cast<float2*>(&part[r0 * NOUT + col])       = make_float2(acc[j][0], acc[j][1]);
            *reinterpret_cast<float2*>(&part[(r0 + 8) * NOUT + col]) = make_float2(acc[j][2], acc[j][3]);
        }
    }

    // ---- per-group barrier: 16 CTAs, release/acquire ticket (wrap-safe) ----
    __syncthreads();
    if (t == 0) {
        unsigned my;
        asm volatile("atom.add.release.gpu.global.u32 %0, [%1], 1;"
                     : "=r"(my) : "l"(&g_tick[grp]) : "memory");
        unsigned target = (my & ~15u) + 16u;
        unsigned cur;
        do {
            asm volatile("ld.acquire.gpu.global.u32 %0, [%1];"
                         : "=r"(cur) : "l"(&g_tick[grp]) : "memory");
        } while ((int)(cur - target) < 0);
    }
    __syncthreads();

    // ---- spread reduce: this CTA handles rows 8q..8q+7 of its group's cols ----
    {
        const int q = bid >> 3;                 // 0..15 within group
        const int row = q * 8 + (t >> 6);       // 8 rows, 64 threads each
        const int col = c0 + (t & 63);          // 64 consecutive cols: coalesced
        const int o = row * NOUT + col;
        float v[KCHUNKS];
        #pragma unroll
        for (int c = 0; c < KCHUNKS; ++c)
            v[c] = g_partial[c * BN + o];
        #pragma unroll
        for (int s = 1; s < KCHUNKS; s <<= 1)
            #pragma unroll
            for (int c = 0; c < KCHUNKS; c += 2 * s)
                v[c] += v[c + s];
        out[o] = v[0] + B[col];
    }
}

extern "C" void kernel_launch(void* const* d_in, const int* in_sizes, int n_in,
                              void* d_out, int out_size)
{
    const float* X = (const float*)d_in[0];  // (128, 1024)
    const float* W = (const float*)d_in[1];  // (1024, 512)
    const float* B = (const float*)d_in[2];  // (512,)
    float* out = (float*)d_out;              // (128, 512)

    cudaFuncSetAttribute(fused_kernel, cudaFuncAttributeMaxDynamicSharedMemorySize, SMEM_BYTES);
    fused_kernel<<<128, NTHR, SMEM_BYTES>>>(X, W, B, out);
}

// round 13
// speedup vs baseline: 1.4469x; 1.0322x over previous
#include <cuda_runtime.h>
#include <cuda_fp16.h>
#include <cstdint>

// y = x @ w + b  (exact collapse of the memristor model; G_off / K_V / k_g all
// cancel).  2-term fp16-split GEMM on legacy mma.sync tensor cores:
//   y = xh@wh + xl@wh  (x = xh + xl exact in fp16; only w-rounding error,
//   rel err ~2e-4, 4x under the 1e-3 gate; fp32 accumulate)
// 128 CTAs x 512 thr = 8 col-tiles x 16 k-chunks (round-8 coordination:
// global release/acquire ticket barrier + all-thread scalar reduce, L2-hot).

#define NIN 1024
#define NOUT 512
#define BATCH 128
#define KCHUNKS 16
#define KCHUNK 64
#define CTILE 64
#define NTHR 512
#define BN (BATCH * NOUT)

#define ASTRIDE 72            // fp16 row stride (144 B) -> conflict-free frags
#define A_ROWS 128
#define B_ROWS 64

#define OFF_AHI 0
#define OFF_ALO (OFF_AHI + A_ROWS * ASTRIDE)
#define OFF_BHI (OFF_ALO + A_ROWS * ASTRIDE)
#define SMEM_ELEMS (OFF_BHI + B_ROWS * ASTRIDE)   // 23040 halfs = 46080 B (static OK)

__device__ float g_partial[KCHUNKS * BN];    // 4 MB scratch
__device__ unsigned g_bar;                   // monotonic ticket

__device__ __forceinline__ uint32_t packh(float a, float b) {
    __half2 h = __floats2half2_rn(a, b);     // a -> low 16 bits
    return *reinterpret_cast<uint32_t*>(&h);
}
__device__ __forceinline__ uint64_t pack64(uint32_t lo, uint32_t hi) {
    uint64_t r; asm("mov.b64 %0, {%1, %2};" : "=l"(r) : "r"(lo), "r"(hi)); return r;
}
__device__ __forceinline__ void mma_f16(float* c, const uint32_t* a, const uint32_t* b) {
    asm volatile(
        "mma.sync.aligned.m16n8k16.row.col.f32.f16.f16.f32 "
        "{%0,%1,%2,%3}, {%4,%5,%6,%7}, {%8,%9}, {%0,%1,%2,%3};"
        : "+f"(c[0]), "+f"(c[1]), "+f"(c[2]), "+f"(c[3])
        : "r"(a[0]), "r"(a[1]), "r"(a[2]), "r"(a[3]), "r"(b[0]), "r"(b[1]));
}

__global__ __launch_bounds__(NTHR) void fused_kernel(
    const float* __restrict__ X, const float* __restrict__ W,
    const float* __restrict__ B, float* __restrict__ out)
{
    __shared__ __half sm[SMEM_ELEMS];
    __half* Ahi = sm + OFF_AHI;
    __half* Alo = sm + OFF_ALO;
    __half* Bhi = sm + OFF_BHI;

    const int t = threadIdx.x, bid = blockIdx.x;
    const int warp = t >> 5, lane = t & 31;
    const int g  = lane >> 2;          // group row 0..7
    const int tq = lane & 3;           // thread-in-group 0..3
    const int c0  = (bid & 7) * CTILE;
    const int kc0 = (bid >> 3) * KCHUNK;      // k-chunk 0..15

    // ---- fill A: X[128 rows x 64 k] -> xh + exact residual xl (fp16).
    //      128*16 float4 = 2048 slots = 4 iters of 512 threads. ----
    #pragma unroll
    for (int i = 0; i < 4; ++i) {
        int idx = t + i * NTHR;                // 0..2047
        int kq = idx & 15, row = idx >> 4;     // row 0..127
        float4 xv = *reinterpret_cast<const float4*>(&X[row * NIN + kc0 + 4 * kq]);
        float h0 = __half2float(__float2half_rn(xv.x));
        float h1 = __half2float(__float2half_rn(xv.y));
        float h2 = __half2float(__float2half_rn(xv.z));
        float h3 = __half2float(__float2half_rn(xv.w));
        int e = row * ASTRIDE + 4 * kq;        // 144*row + 8*kq bytes: 8B-aligned
        *reinterpret_cast<uint64_t*>(&Ahi[e]) = pack64(packh(h0, h1), packh(h2, h3));
        *reinterpret_cast<uint64_t*>(&Alo[e]) =
            pack64(packh(xv.x - h0, xv.y - h1), packh(xv.z - h2, xv.w - h3));
    }
    // ---- fill B: W[64k x 64n] -> [n][k] fp16 pairs. 64n*32kp = 2048 slots. ----
    #pragma unroll
    for (int i = 0; i < 4; ++i) {
        int idx = t + i * NTHR;                // 0..2047
        int n = idx & 63, kp = idx >> 6;       // lanes: consecutive n -> coalesced
        float w0 = W[(kc0 + 2 * kp) * NOUT + c0 + n];
        float w1 = W[(kc0 + 2 * kp + 1) * NOUT + c0 + n];
        *reinterpret_cast<uint32_t*>(&Bhi[n * ASTRIDE + 2 * kp]) = packh(w0, w1);
    }
    __syncthreads();

    // ---- phase 1 compute: warp = rows 16*(w>>1).., cols 32*(w&1).. ----
    float acc[4][4];
    #pragma unroll
    for (int j = 0; j < 4; ++j)
        #pragma unroll
        for (int q = 0; q < 4; ++q) acc[j][q] = 0.f;

    const int wr  = warp >> 1;
    const int cn0 = (warp & 1) * 32;
    const int arow0 = (wr * 16 + g) * ASTRIDE;
    const int arow1 = arow0 + 8 * ASTRIDE;

    #pragma unroll
    for (int kk = 0; kk < 4; ++kk) {
        const int kb = kk * 16 + 2 * tq;
        uint32_t ah[4], al[4];
        ah[0] = *reinterpret_cast<const uint32_t*>(&Ahi[arow0 + kb]);
        ah[1] = *reinterpret_cast<const uint32_t*>(&Ahi[arow1 + kb]);
        ah[2] = *reinterpret_cast<const uint32_t*>(&Ahi[arow0 + kb + 8]);
        ah[3] = *reinterpret_cast<const uint32_t*>(&Ahi[arow1 + kb + 8]);
        al[0] = *reinterpret_cast<const uint32_t*>(&Alo[arow0 + kb]);
        al[1] = *reinterpret_cast<const uint32_t*>(&Alo[arow1 + kb]);
        al[2] = *reinterpret_cast<const uint32_t*>(&Alo[arow0 + kb + 8]);
        al[3] = *reinterpret_cast<const uint32_t*>(&Alo[arow1 + kb + 8]);

        uint32_t bh[4][2];
        #pragma unroll
        for (int j = 0; j < 4; ++j) {
            const int brow = (cn0 + 8 * j + g) * ASTRIDE;
            bh[j][0] = *reinterpret_cast<const uint32_t*>(&Bhi[brow + kb]);
            bh[j][1] = *reinterpret_cast<const uint32_t*>(&Bhi[brow + kb + 8]);
        }
        #pragma unroll
        for (int j = 0; j < 4; ++j) mma_f16(acc[j], ah, bh[j]);
        #pragma unroll
        for (int j = 0; j < 4; ++j) mma_f16(acc[j], al, bh[j]);
    }

    // ---- store partials ----
    {
        float* part = g_partial + (bid >> 3) * BN;
        const int r0 = wr * 16 + g;
        #pragma unroll
        for (int j = 0; j < 4; ++j) {
            const int col = c0 + cn0 + 8 * j + 2 * tq;
            *reinterpret_cast<float2*>(&part[r0 * NOUT + col])       = make_float2(acc[j][0], acc[j][1]);
            *reinterpret_cast<float2*>(&part[(r0 + 8) * NOUT + col]) = make_float2(acc[j][2], acc[j][3]);
        }
    }

    // ---- grid barrier: release/acquire ticket (128 co-resident CTAs) ----
    __syncthreads();
    if (t == 0) {
        unsigned my;
        asm volatile("atom.add.release.gpu.global.u32 %0, [%1], 1;"
                     : "=r"(my) : "l"(&g_bar) : "memory");
        unsigned target = (my & ~127u) + 128u;
        unsigned cur;
        do {
            asm volatile("ld.acquire.gpu.global.u32 %0, [%1];"
                         : "=r"(cur) : "l"(&g_bar) : "memory");
        } while ((int)(cur - target) < 0);
    }
    __syncthreads();

    // ---- phase 2: scalar reduce, all 65536 threads, L2-hot ----
    {
        int gid = bid * NTHR + t;              // 0..65535 == BN
        float v[KCHUNKS];
        #pragma unroll
        for (int c = 0; c < KCHUNKS; ++c)
            v[c] = g_partial[c * BN + gid];
        #pragma unroll
        for (int s = 1; s < KCHUNKS; s <<= 1)
            #pragma unroll
            for (int c = 0; c < KCHUNKS; c += 2 * s)
                v[c] += v[c + s];
        out[gid] = v[0] + B[gid & (NOUT - 1)];
    }
}

extern "C" void kernel_launch(void* const* d_in, const int* in_sizes, int n_in,
                              void* d_out, int out_size)
{
    const float* X = (const float*)d_in[0];  // (128, 1024)
    const float* W = (const float*)d_in[1];  // (1024, 512)
    const float* B = (const float*)d_in[2];  // (512,)
    float* out = (float*)d_out;              // (128, 512)

    fused_kernel<<<128, NTHR>>>(X, W, B, out);
}

// round 14
// speedup vs baseline: 1.6014x; 1.1068x over previous
#include <cuda_runtime.h>
#include <cuda_fp16.h>
#include <cstdint>

// y = x @ w + b  (exact collapse of the memristor model; G_off / K_V / k_g all
// cancel).  2-term fp16-split GEMM on mma.sync tensor cores:
//   y = xh@wh + xl@wh  (x = xh+xl exact in fp16; only w-rounding error ~2e-4)
// NO inter-CTA coordination: grid 128 = 8 row-blocks(16) x 16 col-blocks(32).
// Each CTA does FULL K=1024: its 16 warps take 64-k slices (same per-warp
// tile as the previous best kernel), partials combined by an smem reduce.
// No scratch, no atomics, no barrier -> per-CTA serial path only.

#define NIN 1024
#define NOUT 512
#define BATCH 128
#define NTHR 512

#define XST 1032   // halfs/row: A-frag read banks 4g+tq -> conflict-free
#define WST 1034   // halfs/row: W column-store banks 5n -> conflict-free
#define RST 528    // reduce buffer warp stride (floats), row stride 33

#define OFF_XHI 0
#define OFF_XLO (OFF_XHI + 16 * XST)          // 16512
#define OFF_W   (OFF_XLO + 16 * XST)          // 33024
#define SMEM_HALFS (OFF_W + 32 * WST)         // 66112 halfs = 132224 B
#define SMEM_BYTES (SMEM_HALFS * 2)

__device__ __forceinline__ uint32_t packh(float a, float b) {
    __half2 h = __floats2half2_rn(a, b);      // a -> low 16 bits
    return *reinterpret_cast<uint32_t*>(&h);
}
__device__ __forceinline__ uint64_t pack64(uint32_t lo, uint32_t hi) {
    uint64_t r; asm("mov.b64 %0, {%1, %2};" : "=l"(r) : "r"(lo), "r"(hi)); return r;
}
__device__ __forceinline__ void mma_f16(float* c, const uint32_t* a, const uint32_t* b) {
    asm volatile(
        "mma.sync.aligned.m16n8k16.row.col.f32.f16.f16.f32 "
        "{%0,%1,%2,%3}, {%4,%5,%6,%7}, {%8,%9}, {%0,%1,%2,%3};"
        : "+f"(c[0]), "+f"(c[1]), "+f"(c[2]), "+f"(c[3])
        : "r"(a[0]), "r"(a[1]), "r"(a[2]), "r"(a[3]), "r"(b[0]), "r"(b[1]));
}

__global__ __launch_bounds__(NTHR) void fused_kernel(
    const float* __restrict__ X, const float* __restrict__ W,
    const float* __restrict__ B, float* __restrict__ out)
{
    extern __shared__ __half sm[];
    __half* Xhi = sm + OFF_XHI;
    __half* Xlo = sm + OFF_XLO;
    __half* Wn  = sm + OFF_W;

    const int t = threadIdx.x, bid = blockIdx.x;
    const int warp = t >> 5, lane = t & 31;
    const int g  = lane >> 2;          // group row 0..7
    const int tq = lane & 3;           // thread-in-group 0..3
    const int r0 = (bid >> 4) * 16;    // row block 0..7
    const int c0 = (bid & 15) * 32;    // col block 0..15

    // ---- fill X: 16 rows x 1024 k -> xh + exact fp16 residual xl.
    //      16*256 float4 slots = 4096 = 8 iters of 512 threads. ----
    #pragma unroll
    for (int i = 0; i < 8; ++i) {
        int idx = t + i * NTHR;                 // 0..4095
        int kq = idx & 255, row = idx >> 8;     // kq float4-slot, row 0..15
        float4 xv = *reinterpret_cast<const float4*>(&X[(r0 + row) * NIN + 4 * kq]);
        float h0 = __half2float(__float2half_rn(xv.x));
        float h1 = __half2float(__float2half_rn(xv.y));
        float h2 = __half2float(__float2half_rn(xv.z));
        float h3 = __half2float(__float2half_rn(xv.w));
        int e = row * XST + 4 * kq;             // bytes 2064*row+8*kq: 8B-aligned
        *reinterpret_cast<uint64_t*>(&Xhi[e]) = pack64(packh(h0, h1), packh(h2, h3));
        *reinterpret_cast<uint64_t*>(&Xlo[e]) =
            pack64(packh(xv.x - h0, xv.y - h1), packh(xv.z - h2, xv.w - h3));
    }
    // ---- fill W: 1024 k x 32 n -> [n][k] fp16 pairs. 512 kp * 32 n = 16384
    //      slots = 32 iters.  LDG coalesced over n; STS banks 5n: conflict-free. ----
    #pragma unroll
    for (int i = 0; i < 32; ++i) {
        int idx = t + i * NTHR;                 // 0..16383
        int n = idx & 31, kp = idx >> 5;        // kp 0..511
        float w0 = W[(2 * kp) * NOUT + c0 + n];
        float w1 = W[(2 * kp + 1) * NOUT + c0 + n];
        *reinterpret_cast<uint32_t*>(&Wn[n * WST + 2 * kp]) = packh(w0, w1);
    }
    __syncthreads();

    // ---- compute: warp = FULL 16x32 tile, k slice [warp*64, warp*64+64) ----
    float acc[4][4];
    #pragma unroll
    for (int j = 0; j < 4; ++j)
        #pragma unroll
        for (int q = 0; q < 4; ++q) acc[j][q] = 0.f;

    const int arow0 = g * XST;
    const int arow1 = arow0 + 8 * XST;

    #pragma unroll
    for (int kk = 0; kk < 4; ++kk) {
        const int kb = warp * 64 + kk * 16 + 2 * tq;
        uint32_t ah[4], al[4];
        ah[0] = *reinterpret_cast<const uint32_t*>(&Xhi[arow0 + kb]);
        ah[1] = *reinterpret_cast<const uint32_t*>(&Xhi[arow1 + kb]);
        ah[2] = *reinterpret_cast<const uint32_t*>(&Xhi[arow0 + kb + 8]);
        ah[3] = *reinterpret_cast<const uint32_t*>(&Xhi[arow1 + kb + 8]);
        al[0] = *reinterpret_cast<const uint32_t*>(&Xlo[arow0 + kb]);
        al[1] = *reinterpret_cast<const uint32_t*>(&Xlo[arow1 + kb]);
        al[2] = *reinterpret_cast<const uint32_t*>(&Xlo[arow0 + kb + 8]);
        al[3] = *reinterpret_cast<const uint32_t*>(&Xlo[arow1 + kb + 8]);

        uint32_t bh[4][2];
        #pragma unroll
        for (int j = 0; j < 4; ++j) {
            const int brow = (8 * j + g) * WST;
            bh[j][0] = *reinterpret_cast<const uint32_t*>(&Wn[brow + kb]);
            bh[j][1] = *reinterpret_cast<const uint32_t*>(&Wn[brow + kb + 8]);
        }
        #pragma unroll
        for (int j = 0; j < 4; ++j) mma_f16(acc[j], ah, bh[j]);
        #pragma unroll
        for (int j = 0; j < 4; ++j) mma_f16(acc[j], al, bh[j]);
    }

    // ---- intra-CTA reduce over the 16 k-slices (smem, fixed order) ----
    __syncthreads();                           // tiles no longer needed
    float* red = reinterpret_cast<float*>(sm); // 16 warps x 528 floats = 33.8 KB
    #pragma unroll
    for (int j = 0; j < 4; ++j)
        #pragma unroll
        for (int q = 0; q < 4; ++q) {
            int row = g + 8 * (q >> 1);
            int col = 8 * j + 2 * tq + (q & 1);
            red[warp * RST + row * 33 + col] = acc[j][q];
        }
    __syncthreads();

    // each thread owns one output element of the 16x32 tile
    {
        int row = t >> 5, col = t & 31;
        float v[16];
        #pragma unroll
        for (int w = 0; w < 16; ++w)
            v[w] = red[w * RST + row * 33 + col];
        #pragma unroll
        for (int s = 1; s < 16; s <<= 1)
            #pragma unroll
            for (int c = 0; c < 16; c += 2 * s)
                v[c] += v[c + s];
        out[(r0 + row) * NOUT + c0 + col] = v[0] + B[c0 + col];
    }
}

extern "C" void kernel_launch(void* const* d_in, const int* in_sizes, int n_in,
                              void* d_out, int out_size)
{
    const float* X = (const float*)d_in[0];  // (128, 1024)
    const float* W = (const float*)d_in[1];  // (1024, 512)
    const float* B = (const float*)d_in[2];  // (512,)
    float* out = (float*)d_out;              // (128, 512)

    cudaFuncSetAttribute(fused_kernel, cudaFuncAttributeMaxDynamicSharedMemorySize, SMEM_BYTES);
    fused_kernel<<<128, NTHR, SMEM_BYTES>>>(X, W, B, out);
}